// round 8
// baseline (speedup 1.0000x reference)
#include <cuda_runtime.h>
#include <cuda_fp16.h>

#define NODE_NUM 100000
#define BATCH 4096
#define LAYERS 4
#define EMB 128
#define FEAT 256
#define NEIGH 32
#define PAIRS (BATCH*LAYERS)   // 16384

typedef unsigned long long u64;

// packed fp32x2 helpers (sm_103a FFMA2 — PTX-only per SASS_QUICKREF)
__device__ __forceinline__ u64 pack2(float x) {
    u64 r; asm("mov.b64 %0,{%1,%1};" : "=l"(r) : "f"(x)); return r;
}
__device__ __forceinline__ u64 fma2(u64 a, u64 b, u64 c) {
    u64 d; asm("fma.rn.f32x2 %0,%1,%2,%3;" : "=l"(d) : "l"(a), "l"(b), "l"(c)); return d;
}
__device__ __forceinline__ float2 unpk(u64 v) {
    float lo, hi; asm("mov.b64 {%0,%1},%2;" : "=f"(lo), "=f"(hi) : "l"(v));
    return make_float2(lo, hi);
}

// Scratch (device globals: allocation-free rule).
__device__ __align__(16) __half g_featsh[NODE_NUM * FEAT];  // 51.2 MB
__device__ float  g_sumfeat[PAIRS * FEAT];                  // 16 MB
__device__ float  g_h[PAIRS * EMB];                         // 8 MB

// ---------------------------------------------------------------------------
// K0: convert features fp32 -> fp16
// ---------------------------------------------------------------------------
__global__ __launch_bounds__(256) void k0_convert(const float* __restrict__ feats) {
    const int stride = gridDim.x * blockDim.x;
    const float4* __restrict__ src = (const float4*)feats;
    half2* __restrict__ dst = (half2*)g_featsh;
    const int total4 = NODE_NUM * FEAT / 4;
    for (int k = blockIdx.x * blockDim.x + threadIdx.x; k < total4; k += stride) {
        const float4 v = src[k];
        dst[2 * k]     = __floats2half2_rn(v.x, v.y);
        dst[2 * k + 1] = __floats2half2_rn(v.z, v.w);
    }
}

// ---------------------------------------------------------------------------
// K1: fp16 neighbor gather + sum. Warp per pair.
// ---------------------------------------------------------------------------
__global__ __launch_bounds__(256) void k1_gather_h(const int* __restrict__ neighs) {
    const int tid  = threadIdx.x;
    const int warp = tid >> 5, lane = tid & 31;
    const int p = blockIdx.x * 8 + warp;
    const int myidx = neighs[p * 32 + lane];
    const float4* __restrict__ base = (const float4*)g_featsh;

    float acc[8];
    #pragma unroll
    for (int q = 0; q < 8; q++) acc[q] = 0.f;

    #pragma unroll
    for (int j = 0; j < NEIGH; j++) {
        const int n = __shfl_sync(0xffffffffu, myidx, j);
        const float4 v = base[n * 32 + lane];
        const half2* h2 = (const half2*)&v;
        #pragma unroll
        for (int q = 0; q < 4; q++) {
            const float2 f = __half22float2(h2[q]);
            acc[2 * q]     += f.x;
            acc[2 * q + 1] += f.y;
        }
    }
    float4* dst = (float4*)&g_sumfeat[p * FEAT + lane * 8];
    dst[0] = make_float4(acc[0], acc[1], acc[2], acc[3]);
    dst[1] = make_float4(acc[4], acc[5], acc[6], acc[7]);
}

// ---------------------------------------------------------------------------
// K2: per-layer GEMM  h = sumfeat @ W_l  ([4096,256]@[256,128]), FFMA2.
// Tile M=64 -> grid (64,4)=256 blocks (fills 148 SMs). Thread tile 4x8.
// ---------------------------------------------------------------------------
__global__ __launch_bounds__(256) void k2_gemm(const float* __restrict__ W) {
    const int l  = blockIdx.y;
    const int bm = blockIdx.x;
    __shared__ float As[32][68];    // transposed A tile (64 rows + pad)
    __shared__ float Bs[32][128];

    const int tid = threadIdx.x;
    const int tr = tid >> 4;   // 0..15 -> 4 rows each
    const int tc = tid & 15;   // 0..15 -> 8 cols each

    u64 acc2[2][8];
    #pragma unroll
    for (int i = 0; i < 2; i++)
        #pragma unroll
        for (int j = 0; j < 8; j++) acc2[i][j] = 0ull;

    const float* __restrict__ Wl = W + l * FEAT * EMB;

    for (int k0 = 0; k0 < FEAT; k0 += 32) {
        #pragma unroll
        for (int i = 0; i < 8; i++) {
            const int idx = tid + i * 256;
            const int row = idx >> 5, kk = idx & 31;
            As[kk][row] = g_sumfeat[((bm * 64 + row) * 4 + l) * FEAT + k0 + kk];
        }
        #pragma unroll
        for (int i = 0; i < 16; i++) {
            const int idx = tid + i * 256;
            const int f = idx >> 7, m = idx & 127;
            Bs[f][m] = Wl[(k0 + f) * EMB + m];
        }
        __syncthreads();
        #pragma unroll
        for (int kk = 0; kk < 32; kk++) {
            const u64* a64 = (const u64*)&As[kk][tr * 4];
            u64 a2[2];
            a2[0] = a64[0]; a2[1] = a64[1];
            const float4 bv0 = *(const float4*)&Bs[kk][tc * 8];
            const float4 bv1 = *(const float4*)&Bs[kk][tc * 8 + 4];
            u64 bb[8];
            bb[0] = pack2(bv0.x); bb[1] = pack2(bv0.y);
            bb[2] = pack2(bv0.z); bb[3] = pack2(bv0.w);
            bb[4] = pack2(bv1.x); bb[5] = pack2(bv1.y);
            bb[6] = pack2(bv1.z); bb[7] = pack2(bv1.w);
            #pragma unroll
            for (int i = 0; i < 2; i++)
                #pragma unroll
                for (int j = 0; j < 8; j++)
                    acc2[i][j] = fma2(a2[i], bb[j], acc2[i][j]);
        }
        __syncthreads();
    }
    #pragma unroll
    for (int i2 = 0; i2 < 2; i2++) {
        float r0v[8], r1v[8];
        #pragma unroll
        for (int j = 0; j < 8; j++) {
            const float2 f2 = unpk(acc2[i2][j]);
            r0v[j] = f2.x; r1v[j] = f2.y;
        }
        const int row0 = bm * 64 + tr * 4 + 2 * i2;
        float4* d0 = (float4*)&g_h[(row0 * 4 + l) * EMB + tc * 8];
        d0[0] = make_float4(r0v[0], r0v[1], r0v[2], r0v[3]);
        d0[1] = make_float4(r0v[4], r0v[5], r0v[6], r0v[7]);
        float4* d1 = (float4*)&g_h[((row0 + 1) * 4 + l) * EMB + tc * 8];
        d1[0] = make_float4(r1v[0], r1v[1], r1v[2], r1v[3]);
        d1[1] = make_float4(r1v[4], r1v[5], r1v[6], r1v[7]);
    }
}

// ---------------------------------------------------------------------------
// K34 (fused): tile = 64 pairs (16 batch rows) -> grid 256 blocks.
//   phase1: scores = tanh(H@Ws1).Ws2  (FFMA2, thread tile 4x8)
//   phase2: softmax; phase3: agg; phase4: agg@TW; phase5: residual+normalize
// ---------------------------------------------------------------------------
__global__ __launch_bounds__(256) void k34_fused(const float* __restrict__ Ws1,
                                                 const float* __restrict__ Ws2,
                                                 const float* __restrict__ TW,
                                                 const float* __restrict__ lemb,
                                                 const int* __restrict__ node_i,
                                                 const int* __restrict__ layers,
                                                 float* __restrict__ out) {
    __shared__ float As[32][68];      // phase1 A tiles; phase3/4 aliased as aggs
    __shared__ float Bs[32][128];     // phase1 Ws1 tiles; phase4 TW tiles
    __shared__ float red[64][16];
    __shared__ float scr[64];
    __shared__ float att[16][4];
    __shared__ float w2s[128];

    const int tid = threadIdx.x;
    const int bm = blockIdx.x;          // 256 blocks
    const int pb = bm * 64;             // global pair base
    const int B0 = bm * 16;             // global batch-row base

    if (tid < 128) w2s[tid] = Ws2[tid];
    const int tr = tid >> 4, tc = tid & 15;

    // ---- phase 1: GEMM H@Ws1 with FFMA2 ----
    u64 acc2[2][8];
    #pragma unroll
    for (int i = 0; i < 2; i++)
        #pragma unroll
        for (int j = 0; j < 8; j++) acc2[i][j] = 0ull;

    for (int k0 = 0; k0 < EMB; k0 += 32) {
        #pragma unroll
        for (int i = 0; i < 8; i++) {
            const int idx = tid + i * 256;
            const int row = idx >> 5, kk = idx & 31;
            As[kk][row] = g_h[(pb + row) * EMB + k0 + kk];
        }
        #pragma unroll
        for (int i = 0; i < 16; i++) {
            const int idx = tid + i * 256;
            const int f = idx >> 7, m = idx & 127;
            Bs[f][m] = Ws1[(k0 + f) * EMB + m];
        }
        __syncthreads();
        #pragma unroll
        for (int kk = 0; kk < 32; kk++) {
            const u64* a64 = (const u64*)&As[kk][tr * 4];
            u64 a2[2];
            a2[0] = a64[0]; a2[1] = a64[1];
            const float4 bv0 = *(const float4*)&Bs[kk][tc * 8];
            const float4 bv1 = *(const float4*)&Bs[kk][tc * 8 + 4];
            u64 bb[8];
            bb[0] = pack2(bv0.x); bb[1] = pack2(bv0.y);
            bb[2] = pack2(bv0.z); bb[3] = pack2(bv0.w);
            bb[4] = pack2(bv1.x); bb[5] = pack2(bv1.y);
            bb[6] = pack2(bv1.z); bb[7] = pack2(bv1.w);
            #pragma unroll
            for (int i = 0; i < 2; i++)
                #pragma unroll
                for (int j = 0; j < 8; j++)
                    acc2[i][j] = fma2(a2[i], bb[j], acc2[i][j]);
        }
        __syncthreads();
    }
    // epilogue: tanh + dot Ws2, partial per column-thread
    #pragma unroll
    for (int i2 = 0; i2 < 2; i2++) {
        float p0 = 0.f, p1 = 0.f;
        #pragma unroll
        for (int j = 0; j < 8; j++) {
            const float2 f2 = unpk(acc2[i2][j]);
            const float w = w2s[tc * 8 + j];
            p0 = fmaf(tanhf(f2.x), w, p0);
            p1 = fmaf(tanhf(f2.y), w, p1);
        }
        red[tr * 4 + 2 * i2][tc]     = p0;
        red[tr * 4 + 2 * i2 + 1][tc] = p1;
    }
    __syncthreads();
    if (tid < 64) {
        float s = 0.f;
        #pragma unroll
        for (int c = 0; c < 16; c++) s += red[tid][c];
        scr[tid] = s;
    }
    __syncthreads();

    // ---- phase 2: softmax over 4 layers (16 rows) ----
    if (tid < 16) {
        const float s0 = scr[tid * 4 + 0];
        const float s1 = scr[tid * 4 + 1];
        const float s2 = scr[tid * 4 + 2];
        const float s3 = scr[tid * 4 + 3];
        const float mx = fmaxf(fmaxf(s0, s1), fmaxf(s2, s3));
        const float e0 = __expf(s0 - mx), e1 = __expf(s1 - mx);
        const float e2 = __expf(s2 - mx), e3 = __expf(s3 - mx);
        const float inv = 1.f / (e0 + e1 + e2 + e3);
        att[tid][0] = e0 * inv; att[tid][1] = e1 * inv;
        att[tid][2] = e2 * inv; att[tid][3] = e3 * inv;
    }
    __syncthreads();

    // ---- phase 3: attention-weighted aggregation -> aggs (aliases As) ----
    // aggs[16][132] = 2112 floats <= As capacity (32*68=2176)
    float (*aggs)[132] = (float(*)[132])As;
    {
        const int m = tid & 127;
        const int bh = tid >> 7;            // 0..1
        #pragma unroll
        for (int t = 0; t < 8; t++) {
            const int b = bh * 8 + t;
            const int base = (pb + b * 4) * EMB + m;
            float a = att[b][0] * g_h[base];
            a = fmaf(att[b][1], g_h[base + EMB], a);
            a = fmaf(att[b][2], g_h[base + 2 * EMB], a);
            a = fmaf(att[b][3], g_h[base + 3 * EMB], a);
            aggs[b][m] = a;
        }
    }
    __syncthreads();

    // ---- phase 4: ne = agg @ TW  (16x128 @ 128x128) ----
    // wr = warp (8), 2 rows each; wc = lane (32), 4 cols each
    const int wr = tid >> 5;
    const int wc = tid & 31;
    float acc[2][4];
    #pragma unroll
    for (int i = 0; i < 2; i++)
        #pragma unroll
        for (int j = 0; j < 4; j++) acc[i][j] = 0.f;

    for (int kc = 0; kc < 4; kc++) {
        #pragma unroll
        for (int i = 0; i < 16; i++) {
            const int idx = tid + i * 256;
            const int f = idx >> 7, m = idx & 127;
            Bs[f][m] = TW[(kc * 32 + f) * EMB + m];
        }
        __syncthreads();
        #pragma unroll
        for (int kk = 0; kk < 32; kk++) {
            const int k = kc * 32 + kk;
            float a[2];
            a[0] = aggs[wr * 2][k];
            a[1] = aggs[wr * 2 + 1][k];
            const float4 bv = *(const float4*)&Bs[kk][wc * 4];
            const float b[4] = {bv.x, bv.y, bv.z, bv.w};
            #pragma unroll
            for (int i = 0; i < 2; i++)
                #pragma unroll
                for (int j = 0; j < 4; j++)
                    acc[i][j] = fmaf(a[i], b[j], acc[i][j]);
        }
        __syncthreads();
    }

    // ---- phase 5: residual + L2 normalize (warp-local) ----
    #pragma unroll
    for (int i = 0; i < 2; i++) {
        const int bg = B0 + wr * 2 + i;
        const int li = node_i[bg] * 4 + layers[bg];
        const float4 lv = *(const float4*)&lemb[li * EMB + wc * 4];
        float f[4];
        f[0] = acc[i][0] + lv.x;
        f[1] = acc[i][1] + lv.y;
        f[2] = acc[i][2] + lv.z;
        f[3] = acc[i][3] + lv.w;
        float v = f[0]*f[0] + f[1]*f[1] + f[2]*f[2] + f[3]*f[3];
        #pragma unroll
        for (int off = 16; off > 0; off >>= 1)
            v += __shfl_xor_sync(0xffffffffu, v, off);
        const float inv = 1.f / fmaxf(sqrtf(v), 1e-12f);
        float4 o;
        o.x = f[0] * inv; o.y = f[1] * inv; o.z = f[2] * inv; o.w = f[3] * inv;
        *(float4*)&out[bg * EMB + wc * 4] = o;
    }
}

// ---------------------------------------------------------------------------
extern "C" void kernel_launch(void* const* d_in, const int* in_sizes, int n_in,
                              void* d_out, int out_size) {
    const int*   layers  = (const int*)d_in[0];
    const int*   node_i  = (const int*)d_in[1];
    const int*   neighs  = (const int*)d_in[2];
    const float* feats   = (const float*)d_in[3];
    const float* lemb    = (const float*)d_in[4];
    const float* net     = (const float*)d_in[5];
    const float* TW      = (const float*)d_in[6];
    const float* Ws1     = (const float*)d_in[7];
    const float* Ws2     = (const float*)d_in[8];
    float* out = (float*)d_out;

    k0_convert<<<2048, 256>>>(feats);
    k1_gather_h<<<PAIRS / 8, 256>>>(neighs);
    k2_gemm<<<dim3(BATCH / 64, LAYERS), 256>>>(net);
    k34_fused<<<PAIRS / 64, 256>>>(Ws1, Ws2, TW, lemb, node_i, layers, out);
}

// round 9
// speedup vs baseline: 1.1976x; 1.1976x over previous
#include <cuda_runtime.h>
#include <cuda_fp16.h>

#define NODE_NUM 100000
#define BATCH 4096
#define LAYERS 4
#define EMB 128
#define FEAT 256
#define NEIGH 32
#define PAIRS (BATCH*LAYERS)   // 16384

typedef unsigned long long u64;

// packed fp32x2 helpers (sm_103a FFMA2 — PTX-only per SASS_QUICKREF)
__device__ __forceinline__ u64 pack2(float x) {
    u64 r; asm("mov.b64 %0,{%1,%1};" : "=l"(r) : "f"(x)); return r;
}
__device__ __forceinline__ u64 fma2(u64 a, u64 b, u64 c) {
    u64 d; asm("fma.rn.f32x2 %0,%1,%2,%3;" : "=l"(d) : "l"(a), "l"(b), "l"(c)); return d;
}
__device__ __forceinline__ float2 unpk(u64 v) {
    float lo, hi; asm("mov.b64 {%0,%1},%2;" : "=f"(lo), "=f"(hi) : "l"(v));
    return make_float2(lo, hi);
}

// Scratch (device globals: allocation-free rule).
__device__ __align__(16) __half g_featsh[NODE_NUM * FEAT];  // 51.2 MB
__device__ float  g_sumfeat[PAIRS * FEAT];                  // 16 MB
__device__ float  g_h[PAIRS * EMB];                         // 8 MB

// ---------------------------------------------------------------------------
// K0: convert features fp32 -> fp16
// ---------------------------------------------------------------------------
__global__ __launch_bounds__(256) void k0_convert(const float* __restrict__ feats) {
    const int stride = gridDim.x * blockDim.x;
    const float4* __restrict__ src = (const float4*)feats;
    half2* __restrict__ dst = (half2*)g_featsh;
    const int total4 = NODE_NUM * FEAT / 4;
    for (int k = blockIdx.x * blockDim.x + threadIdx.x; k < total4; k += stride) {
        const float4 v = src[k];
        dst[2 * k]     = __floats2half2_rn(v.x, v.y);
        dst[2 * k + 1] = __floats2half2_rn(v.z, v.w);
    }
}

// ---------------------------------------------------------------------------
// K1: fp16 neighbor gather + sum. Warp per pair.
// ---------------------------------------------------------------------------
__global__ __launch_bounds__(256) void k1_gather_h(const int* __restrict__ neighs) {
    const int tid  = threadIdx.x;
    const int warp = tid >> 5, lane = tid & 31;
    const int p = blockIdx.x * 8 + warp;
    const int myidx = neighs[p * 32 + lane];
    const float4* __restrict__ base = (const float4*)g_featsh;

    float acc[8];
    #pragma unroll
    for (int q = 0; q < 8; q++) acc[q] = 0.f;

    #pragma unroll
    for (int j = 0; j < NEIGH; j++) {
        const int n = __shfl_sync(0xffffffffu, myidx, j);
        const float4 v = base[n * 32 + lane];
        const half2* h2 = (const half2*)&v;
        #pragma unroll
        for (int q = 0; q < 4; q++) {
            const float2 f = __half22float2(h2[q]);
            acc[2 * q]     += f.x;
            acc[2 * q + 1] += f.y;
        }
    }
    float4* dst = (float4*)&g_sumfeat[p * FEAT + lane * 8];
    dst[0] = make_float4(acc[0], acc[1], acc[2], acc[3]);
    dst[1] = make_float4(acc[4], acc[5], acc[6], acc[7]);
}

// ---------------------------------------------------------------------------
// K2: per-layer GEMM  h = sumfeat @ W_l ([4096,256]@[256,128]), FFMA2.
// M=128 tile, grid (32,4)=128 blocks, 8x8 thread tile, register-staged
// double buffering: prefetch stage k+1 LDGs before computing stage k.
// ---------------------------------------------------------------------------
__global__ __launch_bounds__(256) void k2_gemm(const float* __restrict__ W) {
    const int l  = blockIdx.y;
    const int bm = blockIdx.x;
    __shared__ float As[32][132];
    __shared__ float Bs[32][128];

    const int tid = threadIdx.x;
    const int tr = tid >> 4;
    const int tc = tid & 15;

    u64 acc2[4][8];
    #pragma unroll
    for (int i = 0; i < 4; i++)
        #pragma unroll
        for (int j = 0; j < 8; j++) acc2[i][j] = 0ull;

    const float* __restrict__ Wl = W + l * FEAT * EMB;

    // per-thread load index precompute
    int arow[16], akk[16], bf[16], bm_[16];
    #pragma unroll
    for (int i = 0; i < 16; i++) {
        const int idx = tid + i * 256;
        arow[i] = idx >> 5;  akk[i] = idx & 31;
        bf[i]   = idx >> 7;  bm_[i] = idx & 127;
    }

    float rA[16], rB[16];
    // prologue: stage 0 loads
    #pragma unroll
    for (int i = 0; i < 16; i++) {
        rA[i] = g_sumfeat[((bm * 128 + arow[i]) * 4 + l) * FEAT + akk[i]];
        rB[i] = Wl[bf[i] * EMB + bm_[i]];
    }
    #pragma unroll
    for (int i = 0; i < 16; i++) { As[akk[i]][arow[i]] = rA[i]; Bs[bf[i]][bm_[i]] = rB[i]; }
    __syncthreads();

    for (int k0 = 0; k0 < FEAT; k0 += 32) {
        // prefetch next stage into registers (overlaps compute below)
        const int kn = k0 + 32;
        if (kn < FEAT) {
            #pragma unroll
            for (int i = 0; i < 16; i++) {
                rA[i] = g_sumfeat[((bm * 128 + arow[i]) * 4 + l) * FEAT + kn + akk[i]];
                rB[i] = Wl[(kn + bf[i]) * EMB + bm_[i]];
            }
        }
        #pragma unroll
        for (int kk = 0; kk < 32; kk++) {
            const u64* a64 = (const u64*)&As[kk][tr * 8];
            u64 a2[4];
            #pragma unroll
            for (int i = 0; i < 4; i++) a2[i] = a64[i];
            const float4 bv0 = *(const float4*)&Bs[kk][tc * 8];
            const float4 bv1 = *(const float4*)&Bs[kk][tc * 8 + 4];
            u64 bb[8];
            bb[0] = pack2(bv0.x); bb[1] = pack2(bv0.y);
            bb[2] = pack2(bv0.z); bb[3] = pack2(bv0.w);
            bb[4] = pack2(bv1.x); bb[5] = pack2(bv1.y);
            bb[6] = pack2(bv1.z); bb[7] = pack2(bv1.w);
            #pragma unroll
            for (int i = 0; i < 4; i++)
                #pragma unroll
                for (int j = 0; j < 8; j++)
                    acc2[i][j] = fma2(a2[i], bb[j], acc2[i][j]);
        }
        __syncthreads();
        if (kn < FEAT) {
            #pragma unroll
            for (int i = 0; i < 16; i++) { As[akk[i]][arow[i]] = rA[i]; Bs[bf[i]][bm_[i]] = rB[i]; }
            __syncthreads();
        }
    }
    #pragma unroll
    for (int i2 = 0; i2 < 4; i2++) {
        float r0v[8], r1v[8];
        #pragma unroll
        for (int j = 0; j < 8; j++) {
            const float2 f2 = unpk(acc2[i2][j]);
            r0v[j] = f2.x; r1v[j] = f2.y;
        }
        const int row0 = bm * 128 + tr * 8 + 2 * i2;
        float4* d0 = (float4*)&g_h[(row0 * 4 + l) * EMB + tc * 8];
        d0[0] = make_float4(r0v[0], r0v[1], r0v[2], r0v[3]);
        d0[1] = make_float4(r0v[4], r0v[5], r0v[6], r0v[7]);
        float4* d1 = (float4*)&g_h[((row0 + 1) * 4 + l) * EMB + tc * 8];
        d1[0] = make_float4(r1v[0], r1v[1], r1v[2], r1v[3]);
        d1[1] = make_float4(r1v[4], r1v[5], r1v[6], r1v[7]);
    }
}

// ---------------------------------------------------------------------------
// K34 (fused): tile = 128 pairs (32 batch rows), grid 128 blocks.
// phase1 GEMM has register-staged double buffering like K2.
// ---------------------------------------------------------------------------
__global__ __launch_bounds__(256) void k34_fused(const float* __restrict__ Ws1,
                                                 const float* __restrict__ Ws2,
                                                 const float* __restrict__ TW,
                                                 const float* __restrict__ lemb,
                                                 const int* __restrict__ node_i,
                                                 const int* __restrict__ layers,
                                                 float* __restrict__ out) {
    __shared__ float As[32][132];
    __shared__ float Bs[32][128];
    __shared__ float red[128][16];
    __shared__ float scr[128];
    __shared__ float att[32][4];
    __shared__ float w2s[128];

    const int tid = threadIdx.x;
    const int bm = blockIdx.x;
    const int pb = bm * 128;
    const int B0 = bm * 32;

    if (tid < 128) w2s[tid] = Ws2[tid];
    const int tr = tid >> 4, tc = tid & 15;

    // ---- phase 1: GEMM H@Ws1 with FFMA2 + prefetch ----
    u64 acc2[4][8];
    #pragma unroll
    for (int i = 0; i < 4; i++)
        #pragma unroll
        for (int j = 0; j < 8; j++) acc2[i][j] = 0ull;

    int arow[16], akk[16], bf[16], bm_[16];
    #pragma unroll
    for (int i = 0; i < 16; i++) {
        const int idx = tid + i * 256;
        arow[i] = idx >> 5;  akk[i] = idx & 31;
        bf[i]   = idx >> 7;  bm_[i] = idx & 127;
    }

    float rA[16], rB[16];
    #pragma unroll
    for (int i = 0; i < 16; i++) {
        rA[i] = g_h[(pb + arow[i]) * EMB + akk[i]];
        rB[i] = Ws1[bf[i] * EMB + bm_[i]];
    }
    #pragma unroll
    for (int i = 0; i < 16; i++) { As[akk[i]][arow[i]] = rA[i]; Bs[bf[i]][bm_[i]] = rB[i]; }
    __syncthreads();

    for (int k0 = 0; k0 < EMB; k0 += 32) {
        const int kn = k0 + 32;
        if (kn < EMB) {
            #pragma unroll
            for (int i = 0; i < 16; i++) {
                rA[i] = g_h[(pb + arow[i]) * EMB + kn + akk[i]];
                rB[i] = Ws1[(kn + bf[i]) * EMB + bm_[i]];
            }
        }
        #pragma unroll
        for (int kk = 0; kk < 32; kk++) {
            const u64* a64 = (const u64*)&As[kk][tr * 8];
            u64 a2[4];
            #pragma unroll
            for (int i = 0; i < 4; i++) a2[i] = a64[i];
            const float4 bv0 = *(const float4*)&Bs[kk][tc * 8];
            const float4 bv1 = *(const float4*)&Bs[kk][tc * 8 + 4];
            u64 bb[8];
            bb[0] = pack2(bv0.x); bb[1] = pack2(bv0.y);
            bb[2] = pack2(bv0.z); bb[3] = pack2(bv0.w);
            bb[4] = pack2(bv1.x); bb[5] = pack2(bv1.y);
            bb[6] = pack2(bv1.z); bb[7] = pack2(bv1.w);
            #pragma unroll
            for (int i = 0; i < 4; i++)
                #pragma unroll
                for (int j = 0; j < 8; j++)
                    acc2[i][j] = fma2(a2[i], bb[j], acc2[i][j]);
        }
        __syncthreads();
        if (kn < EMB) {
            #pragma unroll
            for (int i = 0; i < 16; i++) { As[akk[i]][arow[i]] = rA[i]; Bs[bf[i]][bm_[i]] = rB[i]; }
            __syncthreads();
        }
    }
    // epilogue: tanh + dot Ws2, partial per column-thread
    #pragma unroll
    for (int i2 = 0; i2 < 4; i2++) {
        float p0 = 0.f, p1 = 0.f;
        #pragma unroll
        for (int j = 0; j < 8; j++) {
            const float2 f2 = unpk(acc2[i2][j]);
            const float w = w2s[tc * 8 + j];
            p0 = fmaf(tanhf(f2.x), w, p0);
            p1 = fmaf(tanhf(f2.y), w, p1);
        }
        red[tr * 8 + 2 * i2][tc]     = p0;
        red[tr * 8 + 2 * i2 + 1][tc] = p1;
    }
    __syncthreads();
    if (tid < 128) {
        float s = 0.f;
        #pragma unroll
        for (int c = 0; c < 16; c++) s += red[tid][c];
        scr[tid] = s;
    }
    __syncthreads();

    // ---- phase 2: softmax over 4 layers ----
    if (tid < 32) {
        const float s0 = scr[tid * 4 + 0];
        const float s1 = scr[tid * 4 + 1];
        const float s2 = scr[tid * 4 + 2];
        const float s3 = scr[tid * 4 + 3];
        const float mx = fmaxf(fmaxf(s0, s1), fmaxf(s2, s3));
        const float e0 = __expf(s0 - mx), e1 = __expf(s1 - mx);
        const float e2 = __expf(s2 - mx), e3 = __expf(s3 - mx);
        const float inv = 1.f / (e0 + e1 + e2 + e3);
        att[tid][0] = e0 * inv; att[tid][1] = e1 * inv;
        att[tid][2] = e2 * inv; att[tid][3] = e3 * inv;
    }
    __syncthreads();

    // ---- phase 3: attention-weighted aggregation -> aggs (aliases As) ----
    float (*aggs)[132] = (float(*)[132])As;
    {
        const int m = tid & 127;
        const int bh = tid >> 7;
        #pragma unroll
        for (int t = 0; t < 16; t++) {
            const int b = bh * 16 + t;
            const int base = (pb + b * 4) * EMB + m;
            float a = att[b][0] * g_h[base];
            a = fmaf(att[b][1], g_h[base + EMB], a);
            a = fmaf(att[b][2], g_h[base + 2 * EMB], a);
            a = fmaf(att[b][3], g_h[base + 3 * EMB], a);
            aggs[b][m] = a;
        }
    }
    __syncthreads();

    // ---- phase 4: ne = agg @ TW ----
    const int wr = tid >> 5;
    const int wc = tid & 31;
    float acc[4][4];
    #pragma unroll
    for (int i = 0; i < 4; i++)
        #pragma unroll
        for (int j = 0; j < 4; j++) acc[i][j] = 0.f;

    for (int kc = 0; kc < 4; kc++) {
        #pragma unroll
        for (int i = 0; i < 16; i++) {
            const int idx = tid + i * 256;
            const int f = idx >> 7, m = idx & 127;
            Bs[f][m] = TW[(kc * 32 + f) * EMB + m];
        }
        __syncthreads();
        #pragma unroll
        for (int kk = 0; kk < 32; kk++) {
            const int k = kc * 32 + kk;
            float a[4];
            #pragma unroll
            for (int i = 0; i < 4; i++) a[i] = aggs[wr * 4 + i][k];
            const float4 bv = *(const float4*)&Bs[kk][wc * 4];
            const float b[4] = {bv.x, bv.y, bv.z, bv.w};
            #pragma unroll
            for (int i = 0; i < 4; i++)
                #pragma unroll
                for (int j = 0; j < 4; j++)
                    acc[i][j] = fmaf(a[i], b[j], acc[i][j]);
        }
        __syncthreads();
    }

    // ---- phase 5: residual + L2 normalize (warp-local) ----
    #pragma unroll
    for (int i = 0; i < 4; i++) {
        const int bg = B0 + wr * 4 + i;
        const int li = node_i[bg] * 4 + layers[bg];
        const float4 lv = *(const float4*)&lemb[li * EMB + wc * 4];
        float f[4];
        f[0] = acc[i][0] + lv.x;
        f[1] = acc[i][1] + lv.y;
        f[2] = acc[i][2] + lv.z;
        f[3] = acc[i][3] + lv.w;
        float v = f[0]*f[0] + f[1]*f[1] + f[2]*f[2] + f[3]*f[3];
        #pragma unroll
        for (int off = 16; off > 0; off >>= 1)
            v += __shfl_xor_sync(0xffffffffu, v, off);
        const float inv = 1.f / fmaxf(sqrtf(v), 1e-12f);
        float4 o;
        o.x = f[0] * inv; o.y = f[1] * inv; o.z = f[2] * inv; o.w = f[3] * inv;
        *(float4*)&out[bg * EMB + wc * 4] = o;
    }
}

// ---------------------------------------------------------------------------
extern "C" void kernel_launch(void* const* d_in, const int* in_sizes, int n_in,
                              void* d_out, int out_size) {
    const int*   layers  = (const int*)d_in[0];
    const int*   node_i  = (const int*)d_in[1];
    const int*   neighs  = (const int*)d_in[2];
    const float* feats   = (const float*)d_in[3];
    const float* lemb    = (const float*)d_in[4];
    const float* net     = (const float*)d_in[5];
    const float* TW      = (const float*)d_in[6];
    const float* Ws1     = (const float*)d_in[7];
    const float* Ws2     = (const float*)d_in[8];
    float* out = (float*)d_out;

    k0_convert<<<2048, 256>>>(feats);
    k1_gather_h<<<PAIRS / 8, 256>>>(neighs);
    k2_gemm<<<dim3(BATCH / 128, LAYERS), 256>>>(net);
    k34_fused<<<PAIRS / 128, 256>>>(Ws1, Ws2, TW, lemb, node_i, layers, out);
}

// round 10
// speedup vs baseline: 1.7415x; 1.4541x over previous
#include <cuda_runtime.h>
#include <cuda_fp16.h>
#include <cstdint>

#define NODE_NUM 100000
#define BATCH 4096
#define LAYERS 4
#define EMB 128
#define FEAT 256
#define NEIGH 32
#define PAIRS (BATCH*LAYERS)   // 16384

// Scratch (device globals: allocation-free rule)
__device__ __align__(16) __half g_featsh[NODE_NUM * FEAT];  // 51.2 MB
__device__ __align__(16) __half g_sumfh[PAIRS * FEAT];      // 8 MB  (fp16 sumfeat)
__device__ __align__(16) float  g_h[PAIRS * EMB];           // 8 MB  (fp32 h)
__device__ __align__(16) __half g_hh[PAIRS * EMB];          // 4 MB  (fp16 h)
__device__ __align__(16) __half g_neth[LAYERS * FEAT * EMB];// 256 KB
__device__ __align__(16) __half g_ws1h[EMB * EMB];          // 32 KB

// ---------------------------------------------------------------------------
// helpers
// ---------------------------------------------------------------------------
__device__ __forceinline__ uint32_t s2u(const void* p) {
    return (uint32_t)__cvta_generic_to_shared(p);
}
__device__ __forceinline__ void ldm4(uint32_t& r0, uint32_t& r1, uint32_t& r2,
                                     uint32_t& r3, uint32_t addr) {
    asm volatile("ldmatrix.sync.aligned.m8n8.x4.shared.b16 {%0,%1,%2,%3},[%4];"
                 : "=r"(r0), "=r"(r1), "=r"(r2), "=r"(r3) : "r"(addr));
}
__device__ __forceinline__ void ldm4t(uint32_t& r0, uint32_t& r1, uint32_t& r2,
                                      uint32_t& r3, uint32_t addr) {
    asm volatile("ldmatrix.sync.aligned.m8n8.x4.trans.shared.b16 {%0,%1,%2,%3},[%4];"
                 : "=r"(r0), "=r"(r1), "=r"(r2), "=r"(r3) : "r"(addr));
}
__device__ __forceinline__ void mma16816(float* c, uint32_t a0, uint32_t a1,
                                         uint32_t a2, uint32_t a3,
                                         uint32_t b0, uint32_t b1) {
    asm volatile(
        "mma.sync.aligned.m16n8k16.row.col.f32.f16.f16.f32 "
        "{%0,%1,%2,%3},{%4,%5,%6,%7},{%8,%9},{%0,%1,%2,%3};"
        : "+f"(c[0]), "+f"(c[1]), "+f"(c[2]), "+f"(c[3])
        : "r"(a0), "r"(a1), "r"(a2), "r"(a3), "r"(b0), "r"(b1));
}
__device__ __forceinline__ uint32_t h2u(float a, float b) {
    __half2 h = __floats2half2_rn(a, b);
    return *(uint32_t*)&h;
}

// ---------------------------------------------------------------------------
// K0: features fp32 -> fp16
// ---------------------------------------------------------------------------
__global__ __launch_bounds__(256) void k0_convert(const float* __restrict__ feats) {
    const int stride = gridDim.x * blockDim.x;
    const float4* __restrict__ src = (const float4*)feats;
    uint2* __restrict__ dst = (uint2*)g_featsh;
    const int total4 = NODE_NUM * FEAT / 4;
    for (int k = blockIdx.x * blockDim.x + threadIdx.x; k < total4; k += stride) {
        const float4 v = src[k];
        uint2 o; o.x = h2u(v.x, v.y); o.y = h2u(v.z, v.w);
        dst[k] = o;
    }
}

// ---------------------------------------------------------------------------
// K0b: convert net [4][256][128] and Ws1 [128][128] to fp16. grid 144 x 256.
// ---------------------------------------------------------------------------
__global__ __launch_bounds__(256) void k0b_convert(const float* __restrict__ net,
                                                   const float* __restrict__ ws1) {
    const int t = blockIdx.x * blockDim.x + threadIdx.x;   // 0..36863
    const int netN4 = LAYERS * FEAT * EMB / 4;             // 32768
    if (t < netN4) {
        const float4 v = ((const float4*)net)[t];
        uint2 o; o.x = h2u(v.x, v.y); o.y = h2u(v.z, v.w);
        ((uint2*)g_neth)[t] = o;
    } else {
        const int u = t - netN4;                           // < 4096
        const float4 v = ((const float4*)ws1)[u];
        uint2 o; o.x = h2u(v.x, v.y); o.y = h2u(v.z, v.w);
        ((uint2*)g_ws1h)[u] = o;
    }
}

// ---------------------------------------------------------------------------
// K1: fp16 gather + sum (fp32 accum), stores fp16 sumfeat. Warp per pair.
// ---------------------------------------------------------------------------
__global__ __launch_bounds__(256) void k1_gather_h(const int* __restrict__ neighs) {
    const int tid  = threadIdx.x;
    const int warp = tid >> 5, lane = tid & 31;
    const int p = blockIdx.x * 8 + warp;
    const int myidx = neighs[p * 32 + lane];
    const float4* __restrict__ base = (const float4*)g_featsh;

    float acc[8];
    #pragma unroll
    for (int q = 0; q < 8; q++) acc[q] = 0.f;

    #pragma unroll
    for (int j = 0; j < NEIGH; j++) {
        const int n = __shfl_sync(0xffffffffu, myidx, j);
        const float4 v = base[n * 32 + lane];
        const half2* h2 = (const half2*)&v;
        #pragma unroll
        for (int q = 0; q < 4; q++) {
            const float2 f = __half22float2(h2[q]);
            acc[2 * q]     += f.x;
            acc[2 * q + 1] += f.y;
        }
    }
    uint4 o;
    o.x = h2u(acc[0], acc[1]); o.y = h2u(acc[2], acc[3]);
    o.z = h2u(acc[4], acc[5]); o.w = h2u(acc[6], acc[7]);
    *(uint4*)&g_sumfh[p * FEAT + lane * 8] = o;
}

// ---------------------------------------------------------------------------
// K2: per-layer GEMM h = sumfeat @ W_l via HMMA m16n8k16.
// grid (64, 4). block 256 (8 warps). Tile M=64 rows, N=128, K=256 (4 chunks of 64).
// Warp w: m-tile (w&3)*16, n-half (w>>2)*64. Writes g_h fp32 + g_hh fp16.
// ---------------------------------------------------------------------------
__global__ __launch_bounds__(256) void k2_gemm() {
    __shared__ __align__(16) __half Ah[64][72];    // 9216 B
    __shared__ __align__(16) __half Bh[64][136];   // 17408 B

    const int l  = blockIdx.y;
    const int bm = blockIdx.x;
    const int tid = threadIdx.x;
    const int w = tid >> 5, lane = tid & 31;
    const int m0 = (w & 3) * 16;
    const int n0 = (w >> 2) * 64;
    const int lq = lane >> 3, lr = lane & 7;
    const int g = lane >> 2, t = lane & 3;

    float acc[8][4];
    #pragma unroll
    for (int i = 0; i < 8; i++)
        #pragma unroll
        for (int j = 0; j < 4; j++) acc[i][j] = 0.f;

    for (int c = 0; c < 4; c++) {          // K chunks of 64
        // stage A: 64x64 halves
        #pragma unroll
        for (int i = 0; i < 2; i++) {
            const int u = tid + i * 256;
            const int row = u >> 3, c8 = u & 7;
            const int pair = (bm * 64 + row) * 4 + l;
            *(uint4*)&Ah[row][c8 * 8] =
                *(const uint4*)&g_sumfh[pair * FEAT + c * 64 + c8 * 8];
        }
        // stage B: 64x128 halves
        #pragma unroll
        for (int i = 0; i < 4; i++) {
            const int u = tid + i * 256;
            const int row = u >> 4, c8 = u & 15;
            *(uint4*)&Bh[row][c8 * 8] =
                *(const uint4*)&g_neth[l * FEAT * EMB + (c * 64 + row) * EMB + c8 * 8];
        }
        __syncthreads();

        #pragma unroll
        for (int ks = 0; ks < 4; ks++) {
            const int kc = ks * 16;
            uint32_t a0, a1, a2, a3;
            ldm4(a0, a1, a2, a3,
                 s2u(&Ah[m0 + lr + (lq & 1) * 8][kc + (lq >> 1) * 8]));
            #pragma unroll
            for (int jn = 0; jn < 4; jn++) {
                uint32_t b0, b1, b2, b3;
                ldm4t(b0, b1, b2, b3,
                      s2u(&Bh[kc + lr + (lq & 1) * 8][n0 + jn * 16 + (lq >> 1) * 8]));
                mma16816(acc[2 * jn],     a0, a1, a2, a3, b0, b1);
                mma16816(acc[2 * jn + 1], a0, a1, a2, a3, b2, b3);
            }
        }
        __syncthreads();
    }

    // epilogue: write fp32 + fp16 h
    #pragma unroll
    for (int jn2 = 0; jn2 < 8; jn2++) {
        const int col = n0 + jn2 * 8 + 2 * t;
        const int row0 = bm * 64 + m0 + g;
        const int pair0 = row0 * 4 + l;
        const int pair1 = (row0 + 8) * 4 + l;
        *(float2*)&g_h[pair0 * EMB + col] = make_float2(acc[jn2][0], acc[jn2][1]);
        *(float2*)&g_h[pair1 * EMB + col] = make_float2(acc[jn2][2], acc[jn2][3]);
        *(uint32_t*)&g_hh[pair0 * EMB + col] = h2u(acc[jn2][0], acc[jn2][1]);
        *(uint32_t*)&g_hh[pair1 * EMB + col] = h2u(acc[jn2][2], acc[jn2][3]);
    }
}

// ---------------------------------------------------------------------------
// K34: tile = 64 pairs (16 batch rows), grid 256 blocks, 256 threads.
// phase1: HMMA scores GEMM (fp16 h @ fp16 Ws1, fp32 acc) + tanh.Ws2 epilogue
// phase2: softmax; phase3: agg (fp32 h); phase4: agg@TW fp32; phase5: normalize
// ---------------------------------------------------------------------------
__global__ __launch_bounds__(256) void k34_fused(const float* __restrict__ Ws2,
                                                 const float* __restrict__ TW,
                                                 const float* __restrict__ lemb,
                                                 const int* __restrict__ node_i,
                                                 const int* __restrict__ layers,
                                                 float* __restrict__ out) {
    __shared__ __align__(16) unsigned char SB[36608];
    __half (*Ah)[72]   = (__half(*)[72])(SB + 0);        // 9216 B  (phase1)
    __half (*Bh)[136]  = (__half(*)[136])(SB + 9216);    // 17408 B (phase1)
    float (*Bs4)[128]  = (float(*)[128])(SB + 0);        // 16384 B (phase4, reuse)
    float (*aggs)[132] = (float(*)[132])(SB + 26624);    // 8448 B
    float (*red)[2]    = (float(*)[2])(SB + 35072);      // 512 B
    float *scr         = (float*)(SB + 35584);           // 256 B
    float (*att)[4]    = (float(*)[4])(SB + 35840);      // 256 B
    float *w2s         = (float*)(SB + 36096);           // 512 B

    const int tid = threadIdx.x;
    const int bm = blockIdx.x;          // 256 blocks
    const int pb = bm * 64;             // pair base
    const int B0 = bm * 16;             // batch-row base

    const int w = tid >> 5, lane = tid & 31;
    const int m0 = (w & 3) * 16;
    const int nh = w >> 2;
    const int n0 = nh * 64;
    const int lq = lane >> 3, lr = lane & 7;
    const int g = lane >> 2, t = lane & 3;

    if (tid < 128) w2s[tid] = Ws2[tid];

    // ---- phase 1: HMMA GEMM h[64x128] @ Ws1[128x128], 2 K-chunks of 64 ----
    float acc[8][4];
    #pragma unroll
    for (int i = 0; i < 8; i++)
        #pragma unroll
        for (int j = 0; j < 4; j++) acc[i][j] = 0.f;

    for (int c = 0; c < 2; c++) {
        #pragma unroll
        for (int i = 0; i < 2; i++) {
            const int u = tid + i * 256;
            const int row = u >> 3, c8 = u & 7;
            *(uint4*)&Ah[row][c8 * 8] =
                *(const uint4*)&g_hh[(pb + row) * EMB + c * 64 + c8 * 8];
        }
        #pragma unroll
        for (int i = 0; i < 4; i++) {
            const int u = tid + i * 256;
            const int row = u >> 4, c8 = u & 15;
            *(uint4*)&Bh[row][c8 * 8] =
                *(const uint4*)&g_ws1h[(c * 64 + row) * EMB + c8 * 8];
        }
        __syncthreads();

        #pragma unroll
        for (int ks = 0; ks < 4; ks++) {
            const int kc = ks * 16;
            uint32_t a0, a1, a2, a3;
            ldm4(a0, a1, a2, a3,
                 s2u(&Ah[m0 + lr + (lq & 1) * 8][kc + (lq >> 1) * 8]));
            #pragma unroll
            for (int jn = 0; jn < 4; jn++) {
                uint32_t b0, b1, b2, b3;
                ldm4t(b0, b1, b2, b3,
                      s2u(&Bh[kc + lr + (lq & 1) * 8][n0 + jn * 16 + (lq >> 1) * 8]));
                mma16816(acc[2 * jn],     a0, a1, a2, a3, b0, b1);
                mma16816(acc[2 * jn + 1], a0, a1, a2, a3, b2, b3);
            }
        }
        __syncthreads();
    }
    // epilogue: tanh + dot with Ws2, reduce over quad lanes
    {
        float p0 = 0.f, p1 = 0.f;
        #pragma unroll
        for (int jn2 = 0; jn2 < 8; jn2++) {
            const int col = n0 + jn2 * 8 + 2 * t;
            p0 += tanhf(acc[jn2][0]) * w2s[col] + tanhf(acc[jn2][1]) * w2s[col + 1];
            p1 += tanhf(acc[jn2][2]) * w2s[col] + tanhf(acc[jn2][3]) * w2s[col + 1];
        }
        p0 += __shfl_xor_sync(0xffffffffu, p0, 1);
        p0 += __shfl_xor_sync(0xffffffffu, p0, 2);
        p1 += __shfl_xor_sync(0xffffffffu, p1, 1);
        p1 += __shfl_xor_sync(0xffffffffu, p1, 2);
        if (t == 0) {
            red[m0 + g][nh]     = p0;
            red[m0 + 8 + g][nh] = p1;
        }
    }
    __syncthreads();
    if (tid < 64) scr[tid] = red[tid][0] + red[tid][1];
    __syncthreads();

    // ---- phase 2: softmax over 4 layers (16 rows) ----
    if (tid < 16) {
        const float s0 = scr[tid * 4 + 0];
        const float s1 = scr[tid * 4 + 1];
        const float s2 = scr[tid * 4 + 2];
        const float s3 = scr[tid * 4 + 3];
        const float mx = fmaxf(fmaxf(s0, s1), fmaxf(s2, s3));
        const float e0 = __expf(s0 - mx), e1 = __expf(s1 - mx);
        const float e2 = __expf(s2 - mx), e3 = __expf(s3 - mx);
        const float inv = 1.f / (e0 + e1 + e2 + e3);
        att[tid][0] = e0 * inv; att[tid][1] = e1 * inv;
        att[tid][2] = e2 * inv; att[tid][3] = e3 * inv;
    }
    __syncthreads();

    // ---- phase 3: attention-weighted aggregation (fp32 h) ----
    {
        const int m = tid & 127;
        const int bh = tid >> 7;
        #pragma unroll
        for (int tt = 0; tt < 8; tt++) {
            const int b = bh * 8 + tt;
            const int base = (pb + b * 4) * EMB + m;
            float a = att[b][0] * g_h[base];
            a = fmaf(att[b][1], g_h[base + EMB], a);
            a = fmaf(att[b][2], g_h[base + 2 * EMB], a);
            a = fmaf(att[b][3], g_h[base + 3 * EMB], a);
            aggs[b][m] = a;
        }
    }
    __syncthreads();

    // ---- phase 4: ne = agg @ TW (16x128 @ 128x128), fp32 ----
    const int wr = tid >> 5;
    const int wc = tid & 31;
    float pa[2][4];
    #pragma unroll
    for (int i = 0; i < 2; i++)
        #pragma unroll
        for (int j = 0; j < 4; j++) pa[i][j] = 0.f;

    for (int kc = 0; kc < 4; kc++) {
        #pragma unroll
        for (int i = 0; i < 16; i++) {
            const int idx = tid + i * 256;
            const int f = idx >> 7, m = idx & 127;
            Bs4[f][m] = TW[(kc * 32 + f) * EMB + m];
        }
        __syncthreads();
        #pragma unroll
        for (int kk = 0; kk < 32; kk++) {
            const int k = kc * 32 + kk;
            const float a0 = aggs[wr * 2][k];
            const float a1 = aggs[wr * 2 + 1][k];
            const float4 bv = *(const float4*)&Bs4[kk][wc * 4];
            pa[0][0] = fmaf(a0, bv.x, pa[0][0]); pa[0][1] = fmaf(a0, bv.y, pa[0][1]);
            pa[0][2] = fmaf(a0, bv.z, pa[0][2]); pa[0][3] = fmaf(a0, bv.w, pa[0][3]);
            pa[1][0] = fmaf(a1, bv.x, pa[1][0]); pa[1][1] = fmaf(a1, bv.y, pa[1][1]);
            pa[1][2] = fmaf(a1, bv.z, pa[1][2]); pa[1][3] = fmaf(a1, bv.w, pa[1][3]);
        }
        __syncthreads();
    }

    // ---- phase 5: residual + L2 normalize (warp-local) ----
    #pragma unroll
    for (int i = 0; i < 2; i++) {
        const int bg = B0 + wr * 2 + i;
        const int li = node_i[bg] * 4 + layers[bg];
        const float4 lv = *(const float4*)&lemb[li * EMB + wc * 4];
        float f[4];
        f[0] = pa[i][0] + lv.x;
        f[1] = pa[i][1] + lv.y;
        f[2] = pa[i][2] + lv.z;
        f[3] = pa[i][3] + lv.w;
        float v = f[0]*f[0] + f[1]*f[1] + f[2]*f[2] + f[3]*f[3];
        #pragma unroll
        for (int off = 16; off > 0; off >>= 1)
            v += __shfl_xor_sync(0xffffffffu, v, off);
        const float inv = 1.f / fmaxf(sqrtf(v), 1e-12f);
        float4 o;
        o.x = f[0] * inv; o.y = f[1] * inv; o.z = f[2] * inv; o.w = f[3] * inv;
        *(float4*)&out[bg * EMB + wc * 4] = o;
    }
}

// ---------------------------------------------------------------------------
extern "C" void kernel_launch(void* const* d_in, const int* in_sizes, int n_in,
                              void* d_out, int out_size) {
    const int*   layers  = (const int*)d_in[0];
    const int*   node_i  = (const int*)d_in[1];
    const int*   neighs  = (const int*)d_in[2];
    const float* feats   = (const float*)d_in[3];
    const float* lemb    = (const float*)d_in[4];
    const float* net     = (const float*)d_in[5];
    const float* TW      = (const float*)d_in[6];
    const float* Ws1     = (const float*)d_in[7];
    const float* Ws2     = (const float*)d_in[8];
    float* out = (float*)d_out;

    k0_convert<<<2048, 256>>>(feats);
    k0b_convert<<<144, 256>>>(net, Ws1);
    k1_gather_h<<<PAIRS / 8, 256>>>(neighs);
    k2_gemm<<<dim3(BATCH / 64, LAYERS), 256>>>();
    k34_fused<<<PAIRS / 64, 256>>>(Ws2, TW, lemb, node_i, layers, out);
}